// round 1
// baseline (speedup 1.0000x reference)
#include <cuda_runtime.h>
#include <cstdint>

// Resample2d / bilinear warp.
// input1: (B=8, C=64, H=256, W=448) float32
// input2: (B=8, 2,    H=256, W=448) float32  (channel 0 = x-flow, 1 = y-flow)
// output: (B=8, C=64, H=256, W=448) float32
//
// One thread per (b, y, x). Bilinear coords/weights computed once, reused
// across all 64 channels. Output stores coalesced; gather loads near-coalesced
// (flow jitter is small vs. 128B line span).

#define RB 8
#define RC 64
#define RH 256
#define RW 448

__global__ __launch_bounds__(256) void resample2d_kernel(
    const float* __restrict__ in1,
    const float* __restrict__ flow,
    float* __restrict__ out)
{
    const int idx = blockIdx.x * blockDim.x + threadIdx.x;
    const int total = RB * RH * RW;
    if (idx >= total) return;

    const int x = idx % RW;
    const int y = (idx / RW) % RH;
    const int b = idx / (RH * RW);

    const int hw = RH * RW;

    // flow lookup
    const float* fp = flow + (size_t)b * 2 * hw + (size_t)y * RW + x;
    const float fx = __ldg(fp);
    const float fy = __ldg(fp + hw);

    const float xf = (float)x + fx;
    const float yf = (float)y + fy;
    const float x0f = floorf(xf);
    const float y0f = floorf(yf);
    const float a  = xf - x0f;   // alpha
    const float bt = yf - y0f;   // beta

    int x0 = (int)x0f;
    int y0 = (int)y0f;
    int x1 = x0 + 1;
    int y1 = y0 + 1;
    x0 = min(max(x0, 0), RW - 1);
    x1 = min(max(x1, 0), RW - 1);
    y0 = min(max(y0, 0), RH - 1);
    y1 = min(max(y1, 0), RH - 1);

    const float w00 = (1.0f - a) * (1.0f - bt);
    const float w01 = a * (1.0f - bt);
    const float w10 = (1.0f - a) * bt;
    const float w11 = a * bt;

    const int i00 = y0 * RW + x0;
    const int i01 = y0 * RW + x1;
    const int i10 = y1 * RW + x0;
    const int i11 = y1 * RW + x1;

    const float* ib = in1 + (size_t)b * RC * hw;
    float* ob = out + (size_t)b * RC * hw + (size_t)y * RW + x;

    #pragma unroll 8
    for (int c = 0; c < RC; c++) {
        const size_t off = (size_t)c * hw;
        const float v00 = __ldg(ib + off + i00);
        const float v01 = __ldg(ib + off + i01);
        const float v10 = __ldg(ib + off + i10);
        const float v11 = __ldg(ib + off + i11);
        ob[off] = w00 * v00 + w01 * v01 + w10 * v10 + w11 * v11;
    }
}

extern "C" void kernel_launch(void* const* d_in, const int* in_sizes, int n_in,
                              void* d_out, int out_size)
{
    const float* in1  = (const float*)d_in[0];
    const float* flow = (const float*)d_in[1];
    float* out = (float*)d_out;

    const int total = RB * RH * RW;       // 917504 spatial locations
    const int threads = 256;
    const int blocks = (total + threads - 1) / threads;
    resample2d_kernel<<<blocks, threads>>>(in1, flow, out);
}

// round 2
// speedup vs baseline: 1.6992x; 1.6992x over previous
#include <cuda_runtime.h>
#include <cstdint>

// Resample2d / bilinear warp, two-pass NHWC strategy.
//
// input1: (B=8, C=64, H=256, W=448) f32 NCHW
// flow:   (B=8, 2,    H=256, W=448) f32
// output: (B=8, C=64, H=256, W=448) f32 NCHW
//
// Pass 1: transpose input1 NCHW -> NHWC scratch (coalesced both sides via smem).
// Pass 2: bilinear gather in NHWC (each tap = 256B contiguous -> zero sector
//         waste), stage per-pixel channel vectors in smem, store NCHW coalesced.

#define RB 8
#define RC 64
#define RH 256
#define RW 448
#define RHW (RH * RW)

__device__ float g_nhwc[RB * RH * RW * RC];   // 235 MB scratch

// ---------------- Pass 1: NCHW -> NHWC transpose ----------------
// grid: (W/32=14, C/32=2, B*H=2048), block 256 (32x8)
__global__ __launch_bounds__(256) void nchw_to_nhwc_kernel(
    const float* __restrict__ in1)
{
    __shared__ float tile[32][33];
    const int t  = threadIdx.x;
    const int tx = t & 31;
    const int ty = t >> 5;              // 0..7
    const int x0 = blockIdx.x * 32;
    const int c0 = blockIdx.y * 32;
    const int by = blockIdx.z;
    const int b  = by >> 8;             // /256
    const int y  = by & 255;

    #pragma unroll
    for (int i = 0; i < 4; i++) {
        const int c = c0 + ty + i * 8;
        tile[ty + i * 8][tx] =
            in1[(((size_t)b * RC + c) * RH + y) * RW + x0 + tx];
    }
    __syncthreads();
    #pragma unroll
    for (int i = 0; i < 4; i++) {
        const int xx = ty + i * 8;
        g_nhwc[(((size_t)b * RH + y) * RW + x0 + xx) * RC + c0 + tx] =
            tile[tx][xx];
    }
}

// ---------------- Pass 2: gather in NHWC, emit NCHW ----------------
// grid: (W/64=7, H=256, B=8), block 256.
// 4 threads per pixel (quad q=0..3 handles channels q*16..q*16+15).
__global__ __launch_bounds__(256) void resample_gather_kernel(
    const float* __restrict__ flow,
    float* __restrict__ out)
{
    __shared__ float spc[64 * 65];      // [pixel][channel], stride 65

    const int t  = threadIdx.x;
    const int p  = t >> 2;              // pixel within tile: 0..63
    const int q  = t & 3;               // channel quad
    const int x0 = blockIdx.x * 64;
    const int y  = blockIdx.y;
    const int b  = blockIdx.z;
    const int x  = x0 + p;

    // flow for this pixel (4 lanes read same address -> broadcast)
    const float* fp = flow + (size_t)b * 2 * RHW + (size_t)y * RW + x;
    const float fx = __ldg(fp);
    const float fy = __ldg(fp + RHW);

    const float xf  = (float)x + fx;
    const float yf  = (float)y + fy;
    const float x0f = floorf(xf);
    const float y0f = floorf(yf);
    const float a   = xf - x0f;
    const float bt  = yf - y0f;

    int xi0 = (int)x0f;
    int yi0 = (int)y0f;
    int xi1 = xi0 + 1;
    int yi1 = yi0 + 1;
    xi0 = min(max(xi0, 0), RW - 1);
    xi1 = min(max(xi1, 0), RW - 1);
    yi0 = min(max(yi0, 0), RH - 1);
    yi1 = min(max(yi1, 0), RH - 1);

    const float w00 = (1.0f - a) * (1.0f - bt);
    const float w01 = a * (1.0f - bt);
    const float w10 = (1.0f - a) * bt;
    const float w11 = a * bt;

    // base in float4 units; each pixel row is RC floats = 16 float4
    const float4* nv = (const float4*)g_nhwc;
    const size_t bbase = (size_t)b * RH * RW;
    const size_t t00 = (bbase + (size_t)yi0 * RW + xi0) * 16 + q * 4;
    const size_t t01 = (bbase + (size_t)yi0 * RW + xi1) * 16 + q * 4;
    const size_t t10 = (bbase + (size_t)yi1 * RW + xi0) * 16 + q * 4;
    const size_t t11 = (bbase + (size_t)yi1 * RW + xi1) * 16 + q * 4;

    float4 acc[4];
    #pragma unroll
    for (int j = 0; j < 4; j++) {
        float4 v00 = __ldg(nv + t00 + j);
        float4 v01 = __ldg(nv + t01 + j);
        float4 v10 = __ldg(nv + t10 + j);
        float4 v11 = __ldg(nv + t11 + j);
        acc[j].x = w00 * v00.x + w01 * v01.x + w10 * v10.x + w11 * v11.x;
        acc[j].y = w00 * v00.y + w01 * v01.y + w10 * v10.y + w11 * v11.y;
        acc[j].z = w00 * v00.z + w01 * v01.z + w10 * v10.z + w11 * v11.z;
        acc[j].w = w00 * v00.w + w01 * v01.w + w10 * v10.w + w11 * v11.w;
    }

    // stage: smem[p*65 + c]
    float* srow = spc + p * 65 + q * 16;
    #pragma unroll
    for (int j = 0; j < 4; j++) {
        srow[j * 4 + 0] = acc[j].x;
        srow[j * 4 + 1] = acc[j].y;
        srow[j * 4 + 2] = acc[j].z;
        srow[j * 4 + 3] = acc[j].w;
    }
    __syncthreads();

    // emit NCHW: 64 threads per channel-row, coalesced 256B stores
    const int px = t & 63;
    const int cg = t >> 6;              // 0..3
    #pragma unroll
    for (int it = 0; it < 16; it++) {
        const int c = it * 4 + cg;
        out[(((size_t)b * RC + c) * RH + y) * RW + x0 + px] =
            spc[px * 65 + c];
    }
}

extern "C" void kernel_launch(void* const* d_in, const int* in_sizes, int n_in,
                              void* d_out, int out_size)
{
    const float* in1  = (const float*)d_in[0];
    const float* flow = (const float*)d_in[1];
    float* out = (float*)d_out;

    dim3 g1(RW / 32, RC / 32, RB * RH);
    nchw_to_nhwc_kernel<<<g1, 256>>>(in1);

    dim3 g2(RW / 64, RH, RB);
    resample_gather_kernel<<<g2, 256>>>(flow, out);
}